// round 1
// baseline (speedup 1.0000x reference)
#include <cuda_runtime.h>
#include <cstdint>

// Problem constants
#define NSESS    4096
#define NTRIALS  2048
#define C_CHUNK  256          // trials per output chunk
#define N_CHUNK  (NTRIALS / C_CHUNK)   // 8
#define WARMUP   64           // warmup trials before each chunk (except chunk 0)
#define TILE     16           // trials per smem tile

// smem layout per warp (one warp per block)
#define ROW_BYTES   (TILE * 12)          // 192 B of raw input per session per tile
#define ROW_CHUNKS  (ROW_BYTES / 16)     // 12 x 16B cp.async chunks per row
#define ROW_STRIDE  208                  // padded row stride (16B-aligned, 4-way LDS conflict)
#define IN_TILE_BYTES  (32 * ROW_STRIDE) // 6656 B per stage
#define OUT_ROW_F   33                   // out staging row stride in floats (conflict-free)
#define OUT_TILE_BYTES (32 * OUT_ROW_F * 4)  // 4224 B
#define SMEM_BYTES  (2 * IN_TILE_BYTES + OUT_TILE_BYTES)  // 17536 B < 48KB

__device__ __forceinline__ void cp_async16(uint32_t dst, const void* src) {
    asm volatile("cp.async.cg.shared.global [%0], [%1], 16;\n"
                 :: "r"(dst), "l"(src));
}
__device__ __forceinline__ void cp_commit() {
    asm volatile("cp.async.commit_group;\n" ::: "memory");
}
__device__ __forceinline__ void cp_wait1() {
    asm volatile("cp.async.wait_group 1;\n" ::: "memory");
}
__device__ __forceinline__ void cp_wait0() {
    asm volatile("cp.async.wait_group 0;\n" ::: "memory");
}

// Issue cp.async for one 32-session x TILE-trial tile.
// src0 points at (sess0, t0, 0); 32 rows of 192B, gmem row stride = NTRIALS*12.
__device__ __forceinline__ void issue_tile(const char* __restrict__ src0,
                                           uint32_t sdst, int lane) {
#pragma unroll
    for (int m = 0; m < 12; m++) {
        int g   = lane + 32 * m;          // 0..383
        int row = g / ROW_CHUNKS;         // 0..31 (session within warp)
        int cc  = g - row * ROW_CHUNKS;   // 0..11 (16B chunk within row)
        cp_async16(sdst + row * ROW_STRIDE + cc * 16,
                   src0 + (long)row * (NTRIALS * 12) + cc * 16);
    }
    cp_commit();
}

__global__ void __launch_bounds__(32)
hmm_filter_kernel(const float* __restrict__ in,
                  const float* __restrict__ p_stay_raw,
                  const float* __restrict__ c_raw,
                  float* __restrict__ out) {
    extern __shared__ char smem[];
    const int lane = threadIdx.x & 31;

    // block -> (session group, chunk)
    const int chunk = blockIdx.x & (N_CHUNK - 1);
    const int sess0 = (blockIdx.x >> 3) * 32;     // N_CHUNK == 8

    // model parameters (broadcast loads, L2 hits)
    const float p  = 1.0f / (1.0f + __expf(-p_stay_raw[0]));
    const float c  = 1.0f / (1.0f + __expf(-c_raw[0]));
    const float A  = 0.5f * (1.0f + c);
    const float B  = 0.5f * (1.0f - c);
    const float q  = 0.5f * (1.0f + p);
    const float qm = 0.5f * (1.0f - p);

    const int t_out0   = chunk * C_CHUNK;
    const int t_start  = (chunk == 0) ? 0 : (t_out0 - WARMUP);
    const int ntiles   = (t_out0 + C_CHUNK - t_start) / TILE;   // 16 or 20
    const int warm_tiles = (t_out0 - t_start) / TILE;           // 0 or 4

    char* in_buf  = smem;
    float* out_buf = (float*)(smem + 2 * IN_TILE_BYTES);
    const uint32_t smem_in = (uint32_t)__cvta_generic_to_shared(in_buf);

    const char* gsrc = (const char*)in + ((long)sess0 * NTRIALS + t_start) * 12;

    // prologue: stage 0
    issue_tile(gsrc, smem_in, lane);

    float v0 = 0.5f, v1 = 0.5f;

    for (int t = 0; t < ntiles; t++) {
        if (t + 1 < ntiles) {
            issue_tile(gsrc + (long)(t + 1) * (TILE * 12),
                       smem_in + ((t + 1) & 1) * IN_TILE_BYTES, lane);
            cp_wait1();
        } else {
            cp_wait0();
        }
        __syncwarp();

        const float* rowp =
            (const float*)(in_buf + (t & 1) * IN_TILE_BYTES + lane * ROW_STRIDE);
        const bool do_out = (t >= warm_tiles);

        float rlast = 1.0f;
#pragma unroll
        for (int i = 0; i < TILE; i++) {
            // raw trial data (off critical path)
            float cl = rowp[3 * i + 0];
            float cr = rowp[3 * i + 1];
            float o  = rowp[3 * i + 2];
            float om = 1.0f - o;
            // evidence row of ev_mat selected/blended generically
            float w0 = fmaf(cl, o,  cr * om);
            float w1 = fmaf(cl, om, cr * o);
            float e0 = fmaf(w0, A, w1 * B);
            float e1 = fmaf(w0, B, w1 * A);
            // unnormalized recurrence: critical chain = 3 F-ops
            float u0 = e0 * v0;
            float u1 = e1 * v1;
            float a  = fmaf(q,  u0, qm * u1);
            float b  = fmaf(qm, u0, q  * u1);
            // normalization (off chain)
            float s  = u0 + u1;
            float r  = 1.0f / s;
            if (do_out) {
                out_buf[lane * OUT_ROW_F + 2 * i + 0] = a * r;
                out_buf[lane * OUT_ROW_F + 2 * i + 1] = b * r;
            }
            v0 = a; v1 = b;
            rlast = r;
        }
        // per-tile renormalization (keeps v in fp32 range)
        v0 *= rlast;
        v1 *= rlast;

        if (do_out) {
            __syncwarp();
            const long tout = (long)t_start + (long)t * TILE;
            float* og = out + (long)sess0 * (NTRIALS * 2) + tout * 2;
            // 32 sessions x 32 floats (2*TILE), coalesced 128B stores
#pragma unroll 4
            for (int j = 0; j < 32; j++) {
                og[(long)j * (NTRIALS * 2) + lane] = out_buf[j * OUT_ROW_F + lane];
            }
            __syncwarp();
        }
    }
}

extern "C" void kernel_launch(void* const* d_in, const int* in_sizes, int n_in,
                              void* d_out, int out_size) {
    const float* in   = (const float*)d_in[0];
    const float* praw = (const float*)d_in[1];
    const float* craw = (const float*)d_in[2];
    float* out = (float*)d_out;

    const int grid = (NSESS / 32) * N_CHUNK;   // 1024 blocks, 1 warp each
    hmm_filter_kernel<<<grid, 32, SMEM_BYTES>>>(in, praw, craw, out);
}